// round 15
// baseline (speedup 1.0000x reference)
#include <cuda_runtime.h>

// GRU_83906481094863 — v14 = v9 + warp phase-staggered k-chunk order.
// B=512, T=1024, D=46, H=128. 128 CTAs x 192 threads, NB=4 batches/CTA.
//   threads [0,128): gate threads (4 warps, 1/SMSP). Thread u owns gate rows
//     {u, u+128, u+256}; hh-dot from smem W (k-chunk-major LDS.128, broadcast
//     h/x), ih-dot from register W_ih. Warp w walks the 32 hh k-chunks in
//     rotated order (kc + 8*w) & 31 -> the 4 warps' load bursts are phase-
//     offset, so the LDS crossbar queue is fed continuously instead of in
//     lockstep floods (v9's convoy: both pipes idle ~40% simultaneously).
//   threads [128,192): aux, prefetch x(t+1). ONE __syncthreads per step.
// MUFU nonlinearities; biases folded into accumulator init (v9-proven).

#define BB 512
#define TT 1024
#define DD 46
#define DP 48
#define HH 128
#define GG 384
#define NB 4
#define NCTA (BB/NB) // 128
#define NTHR 192
#define NGATE 128

// Shared (floats): sW[49152] W_hh k-chunk-major; sH[2][NB][HH]=1024; sX[2][NB][DP]=384
#define SMEM_FLOATS (49152 + 1024 + 384)
#define SMEM_BYTES  (SMEM_FLOATS * 4)

__device__ __forceinline__ void fma2(unsigned long long &d,
                                     unsigned long long a,
                                     unsigned long long b) {
    asm("fma.rn.f32x2 %0, %1, %2, %0;" : "+l"(d) : "l"(a), "l"(b));
}
__device__ __forceinline__ float sum2(unsigned long long v) {
    float lo, hi;
    asm("mov.b64 {%0, %1}, %2;" : "=f"(lo), "=f"(hi) : "l"(v));
    return lo + hi;
}
__device__ __forceinline__ unsigned long long pack2(float lo, float hi) {
    unsigned long long v;
    asm("mov.b64 %0, {%1, %2};" : "=l"(v) : "f"(lo), "f"(hi));
    return v;
}
__device__ __forceinline__ float fast_sig(float x) {
    float e = __expf(-x);
    return __fdividef(1.f, 1.f + e);
}
__device__ __forceinline__ float fast_tanh(float x) {
    x = fminf(15.f, fmaxf(-15.f, x));
    float e = __expf(-2.f * x);
    return __fdividef(1.f - e, 1.f + e);
}

__global__ void __launch_bounds__(NTHR, 1) gru_v14(
    const float* __restrict__ history,  // [B][T][D]
    const float* __restrict__ W_ih,     // [3H][D]
    const float* __restrict__ W_hh,     // [3H][H]
    const float* __restrict__ b_ih,     // [3H]
    const float* __restrict__ b_hh,     // [3H]
    const float* __restrict__ h0,       // [H]
    float* __restrict__ out)            // [B][H]
{
    extern __shared__ float smem[];
    float* sW = smem;            // float4 view: (kc*GG + j)
    float* sH = smem + 49152;    // [2][NB][HH]
    float* sX = sH + 1024;       // [2][NB][DP]

    const int tid = threadIdx.x;
    const int b0  = blockIdx.x * NB;

    // ---- stage W_hh k-chunk-major ----
    for (int idx = tid; idx < GG * HH; idx += NTHR) {
        int j = idx >> 7, k = idx & 127;
        sW[((k >> 2) * GG + j) * 4 + (k & 3)] = W_hh[idx];
    }
    // ---- h(0) ----
    for (int idx = tid; idx < NB * HH; idx += NTHR)
        sH[idx] = h0[idx & 127];
    // ---- zero x pads ----
    if (tid < 16) {
        int buf = tid >> 3, nb = (tid >> 1) & 3, d = DD + (tid & 1);
        sX[buf * (NB * DP) + nb * DP + d] = 0.f;
    }
    // ---- x(0) ----
    for (int idx = tid; idx < NB * DD; idx += NTHR) {
        int nb = idx / DD, d = idx - nb * DD;
        sX[nb * DP + d] = history[(size_t)(b0 + nb) * (TT * DD) + d];
    }

    // ---- gate-thread private state ----
    const int u = tid;
    const int woff = (tid >> 5) << 3;   // warp phase offset: 0,8,16,24
    unsigned long long wih[3][24];
    float brz[2];       // folded r/z bias: b_ih + b_hh
    float bin2, bhn2;   // n-gate biases (must stay separate)
    if (tid < NGATE) {
        brz[0] = b_ih[u] + b_hh[u];
        brz[1] = b_ih[u + HH] + b_hh[u + HH];
        bin2 = b_ih[u + 2 * HH];
        bhn2 = b_hh[u + 2 * HH];
        #pragma unroll
        for (int g = 0; g < 3; g++) {
            const int j = u + g * HH;
            #pragma unroll
            for (int p = 0; p < 23; p++)
                wih[g][p] = pack2(W_ih[j * DD + 2 * p], W_ih[j * DD + 2 * p + 1]);
            wih[g][23] = 0ull;
        }
    }
    const ulonglong2* wrow0 = (const ulonglong2*)sW + u;      // row u
    const ulonglong2* wrow1 = wrow0 + HH;                     // row u+128
    const ulonglong2* wrow2 = wrow0 + 2 * HH;                 // row u+256

    __syncthreads();

    for (int t = 0; t < TT; t++) {
        const int cur = t & 1, nxt = cur ^ 1;

        if (tid < NGATE) {
            const float* hb = sH + cur * (NB * HH);
            const float* xb = sX + cur * (NB * DP);

            // a0/a1: full r/z preactivation; a2: hh part of n; an: ih part of n
            unsigned long long a0[NB], a1[NB], a2[NB], an[NB];
            #pragma unroll
            for (int nb = 0; nb < NB; nb++) {
                a0[nb] = pack2(brz[0], 0.f);
                a1[nb] = pack2(brz[1], 0.f);
                a2[nb] = pack2(bhn2, 0.f);
                an[nb] = pack2(bin2, 0.f);
            }

            // ---- hh-dot: 32 k-chunks, warp-rotated order (anti-convoy) ----
            #pragma unroll 8
            for (int kc = 0; kc < 32; kc++) {
                const int kcr = (kc + woff) & 31;
                ulonglong2 w0 = wrow0[kcr * GG];
                ulonglong2 w1 = wrow1[kcr * GG];
                ulonglong2 w2 = wrow2[kcr * GG];
                ulonglong2 hA = *(const ulonglong2*)(hb + 0 * HH + kcr * 4);
                ulonglong2 hB = *(const ulonglong2*)(hb + 1 * HH + kcr * 4);
                ulonglong2 hC = *(const ulonglong2*)(hb + 2 * HH + kcr * 4);
                ulonglong2 hD = *(const ulonglong2*)(hb + 3 * HH + kcr * 4);
                fma2(a0[0], w0.x, hA.x); fma2(a0[0], w0.y, hA.y);
                fma2(a0[1], w0.x, hB.x); fma2(a0[1], w0.y, hB.y);
                fma2(a0[2], w0.x, hC.x); fma2(a0[2], w0.y, hC.y);
                fma2(a0[3], w0.x, hD.x); fma2(a0[3], w0.y, hD.y);
                fma2(a1[0], w1.x, hA.x); fma2(a1[0], w1.y, hA.y);
                fma2(a1[1], w1.x, hB.x); fma2(a1[1], w1.y, hB.y);
                fma2(a1[2], w1.x, hC.x); fma2(a1[2], w1.y, hC.y);
                fma2(a1[3], w1.x, hD.x); fma2(a1[3], w1.y, hD.y);
                fma2(a2[0], w2.x, hA.x); fma2(a2[0], w2.y, hA.y);
                fma2(a2[1], w2.x, hB.x); fma2(a2[1], w2.y, hB.y);
                fma2(a2[2], w2.x, hC.x); fma2(a2[2], w2.y, hC.y);
                fma2(a2[3], w2.x, hD.x); fma2(a2[3], w2.y, hD.y);
            }
            // ---- ih-dot: r/z merge into a0/a1; n stays in an ----
            #pragma unroll
            for (int q = 0; q < 12; q++) {
                ulonglong2 xA = *(const ulonglong2*)(xb + 0 * DP + 4 * q);
                ulonglong2 xB = *(const ulonglong2*)(xb + 1 * DP + 4 * q);
                ulonglong2 xC = *(const ulonglong2*)(xb + 2 * DP + 4 * q);
                ulonglong2 xD = *(const ulonglong2*)(xb + 3 * DP + 4 * q);
                unsigned long long w0a = wih[0][2*q], w0b = wih[0][2*q+1];
                unsigned long long w1a = wih[1][2*q], w1b = wih[1][2*q+1];
                unsigned long long w2a = wih[2][2*q], w2b = wih[2][2*q+1];
                fma2(a0[0], w0a, xA.x); fma2(a0[0], w0b, xA.y);
                fma2(a0[1], w0a, xB.x); fma2(a0[1], w0b, xB.y);
                fma2(a0[2], w0a, xC.x); fma2(a0[2], w0b, xC.y);
                fma2(a0[3], w0a, xD.x); fma2(a0[3], w0b, xD.y);
                fma2(a1[0], w1a, xA.x); fma2(a1[0], w1b, xA.y);
                fma2(a1[1], w1a, xB.x); fma2(a1[1], w1b, xB.y);
                fma2(a1[2], w1a, xC.x); fma2(a1[2], w1b, xC.y);
                fma2(a1[3], w1a, xD.x); fma2(a1[3], w1b, xD.y);
                fma2(an[0], w2a, xA.x); fma2(an[0], w2b, xA.y);
                fma2(an[1], w2a, xB.x); fma2(an[1], w2b, xB.y);
                fma2(an[2], w2a, xC.x); fma2(an[2], w2b, xC.y);
                fma2(an[3], w2a, xD.x); fma2(an[3], w2b, xD.y);
            }

            // ---- nonlinearity + h update, in-register (MUFU) ----
            float* hn = sH + nxt * (NB * HH);
            #pragma unroll
            for (int nb = 0; nb < NB; nb++) {
                float r = fast_sig(sum2(a0[nb]));
                float z = fast_sig(sum2(a1[nb]));
                float n = fast_tanh(sum2(an[nb]) + r * sum2(a2[nb]));
                float hold = hb[nb * HH + u];
                float hv = n + z * (hold - n);
                hn[nb * HH + u] = hv;
                if (t == TT - 1)
                    out[(size_t)(b0 + nb) * HH + u] = hv;
            }
        } else {
            // ---- aux: prefetch x(t+1) ----
            if (t + 1 < TT) {
                const int a = tid - NGATE;   // 0..63
                #pragma unroll
                for (int r = 0; r < 3; r++) {
                    int idx = a + r * 64;
                    if (idx < NB * DD) {
                        int nb = idx / DD, d = idx - nb * DD;
                        sX[nxt * (NB * DP) + nb * DP + d] =
                            history[(size_t)(b0 + nb) * (TT * DD) + (t + 1) * DD + d];
                    }
                }
            }
        }

        __syncthreads();   // h(t+1) + x(t+1) visible
    }
}

extern "C" void kernel_launch(void* const* d_in, const int* in_sizes, int n_in,
                              void* d_out, int out_size) {
    const float* history = (const float*)d_in[0];
    const float* W_ih    = (const float*)d_in[1];
    const float* W_hh    = (const float*)d_in[2];
    const float* b_ih    = (const float*)d_in[3];
    const float* b_hh    = (const float*)d_in[4];
    const float* h0      = (const float*)d_in[5];
    float* out = (float*)d_out;

    cudaFuncSetAttribute(gru_v14,
                         cudaFuncAttributeMaxDynamicSharedMemorySize, SMEM_BYTES);
    gru_v14<<<NCTA, NTHR, SMEM_BYTES>>>(history, W_ih, W_hh,
                                        b_ih, b_hh, h0, out);
}

// round 16
// speedup vs baseline: 1.0869x; 1.0869x over previous
#include <cuda_runtime.h>

// GRU_83906481094863 — v15 = v13 with DISTANCE-2 (3-buffer) software pipeline.
// B=512, T=1024, D=46, H=128. 128 CTAs x 192 threads, NB=4 batches/CTA.
//   gate threads (tid<128, 4 warps = 1/SMSP): unit u owns rows {u,u+128,u+256}.
//     hh loop: 3 rotating load buffers; chunk kc+2's 7 LDS issue BEFORE chunk
//     kc's 24 fma2 -> ~96 cyc of FMA cover per load vs ~60 cyc effective LDS
//     latency under 4-warp queueing (v13's 1-deep = 48 cyc cover was too
//     shallow, measured null). n-gate W_ih in smem funds the buffer regs.
//     ih tail: r/z register W + n smem W, one loop. MUFU nonlinearities.
//   aux threads (tid 128-191): prefetch x(t+1). ONE __syncthreads per step.

#define BB 512
#define TT 1024
#define DD 46
#define DP 48
#define HH 128
#define GG 384
#define NB 4
#define NCTA (BB/NB) // 128
#define NTHR 192
#define NGATE 128

// Shared floats: sW[49152] W_hh k-chunk-major | sWin[6144] n-gate W_ih staged
//                | sH[2][NB][HH](1024) | sX[2][NB][DP](384)
#define OFF_WIN 49152
#define OFF_H   55296
#define OFF_X   56320
#define SMEM_FLOATS 56704
#define SMEM_BYTES  (SMEM_FLOATS * 4)   // 226816

__device__ __forceinline__ void fma2(unsigned long long &d,
                                     unsigned long long a,
                                     unsigned long long b) {
    asm("fma.rn.f32x2 %0, %1, %2, %0;" : "+l"(d) : "l"(a), "l"(b));
}
__device__ __forceinline__ float sum2(unsigned long long v) {
    float lo, hi;
    asm("mov.b64 {%0, %1}, %2;" : "=f"(lo), "=f"(hi) : "l"(v));
    return lo + hi;
}
__device__ __forceinline__ unsigned long long pack2(float lo, float hi) {
    unsigned long long v;
    asm("mov.b64 %0, {%1, %2};" : "=l"(v) : "f"(lo), "f"(hi));
    return v;
}
__device__ __forceinline__ float fast_sig(float x) {
    float e = __expf(-x);
    return __fdividef(1.f, 1.f + e);
}
__device__ __forceinline__ float fast_tanh(float x) {
    x = fminf(15.f, fmaxf(-15.f, x));
    float e = __expf(-2.f * x);
    return __fdividef(1.f - e, 1.f + e);
}

__global__ void __launch_bounds__(NTHR, 1) gru_v15(
    const float* __restrict__ history,  // [B][T][D]
    const float* __restrict__ W_ih,     // [3H][D]
    const float* __restrict__ W_hh,     // [3H][H]
    const float* __restrict__ b_ih,     // [3H]
    const float* __restrict__ b_hh,     // [3H]
    const float* __restrict__ h0,       // [H]
    float* __restrict__ out)            // [B][H]
{
    extern __shared__ float smem[];
    float* sW   = smem;              // float4 view: (kc*GG + j)
    float* sWin = smem + OFF_WIN;    // float4 view: (q*HH + u), n-gate W_ih
    float* sH   = smem + OFF_H;      // [2][NB][HH]
    float* sX   = smem + OFF_X;      // [2][NB][DP]

    const int tid = threadIdx.x;
    const int b0  = blockIdx.x * NB;

    // ---- stage W_hh k-chunk-major ----
    for (int idx = tid; idx < GG * HH; idx += NTHR) {
        int j = idx >> 7, k = idx & 127;
        sW[((k >> 2) * GG + j) * 4 + (k & 3)] = W_hh[idx];
    }
    // ---- stage n-gate W_ih k-chunk-major (pads k=46,47 zero) ----
    for (int idx = tid; idx < HH * DP; idx += NTHR) {
        int uu = idx / DP, k = idx - uu * DP;
        float v = (k < DD) ? W_ih[(2 * HH + uu) * DD + k] : 0.f;
        sWin[((k >> 2) * HH + uu) * 4 + (k & 3)] = v;
    }
    // ---- h(0) ----
    for (int idx = tid; idx < NB * HH; idx += NTHR)
        sH[idx] = h0[idx & 127];
    // ---- zero x pads ----
    if (tid < 16) {
        int buf = tid >> 3, nb = (tid >> 1) & 3, d = DD + (tid & 1);
        sX[buf * (NB * DP) + nb * DP + d] = 0.f;
    }
    // ---- x(0) ----
    for (int idx = tid; idx < NB * DD; idx += NTHR) {
        int nb = idx / DD, d = idx - nb * DD;
        sX[nb * DP + d] = history[(size_t)(b0 + nb) * (TT * DD) + d];
    }

    // ---- gate-thread private state (r/z W_ih rows only) ----
    const int u = tid;
    unsigned long long wih[2][24];
    float brz0 = 0.f, brz1 = 0.f, bhn = 0.f, bin = 0.f;
    if (tid < NGATE) {
        brz0 = b_ih[u] + b_hh[u];
        brz1 = b_ih[u + HH] + b_hh[u + HH];
        bhn  = b_hh[u + 2 * HH];
        bin  = b_ih[u + 2 * HH];
        #pragma unroll
        for (int g = 0; g < 2; g++) {
            const int j = u + g * HH;
            #pragma unroll
            for (int p = 0; p < 23; p++)
                wih[g][p] = pack2(W_ih[j * DD + 2 * p], W_ih[j * DD + 2 * p + 1]);
            wih[g][23] = 0ull;
        }
    }
    const ulonglong2* wrow0 = (const ulonglong2*)sW + u;      // row u
    const ulonglong2* wrow1 = wrow0 + HH;                     // row u+128
    const ulonglong2* wrow2 = wrow0 + 2 * HH;                 // row u+256
    const ulonglong2* winrow = (const ulonglong2*)sWin + u;   // n-gate ih row

    __syncthreads();

    for (int t = 0; t < TT; t++) {
        const int cur = t & 1, nxt = cur ^ 1;

        if (tid < NGATE) {
            const float* hb = sH + cur * (NB * HH);
            const float* xb = sX + cur * (NB * DP);

            unsigned long long a0[NB], a1[NB], a2[NB], an[NB];
            #pragma unroll
            for (int nb = 0; nb < NB; nb++) {
                a0[nb] = pack2(brz0, 0.f);
                a1[nb] = pack2(brz1, 0.f);
                a2[nb] = pack2(bhn, 0.f);
                an[nb] = pack2(bin, 0.f);
            }

            // ---- hh-dot, distance-2 pipeline with 3 rotating buffers ----
            ulonglong2 Pw0[3], Pw1[3], Pw2[3];
            ulonglong2 PhA[3], PhB[3], PhC[3], PhD[3];
            #pragma unroll
            for (int pl = 0; pl < 2; pl++) {     // preload chunks 0,1
                Pw0[pl] = wrow0[pl * GG];
                Pw1[pl] = wrow1[pl * GG];
                Pw2[pl] = wrow2[pl * GG];
                PhA[pl] = *(const ulonglong2*)(hb + 0 * HH + pl * 4);
                PhB[pl] = *(const ulonglong2*)(hb + 1 * HH + pl * 4);
                PhC[pl] = *(const ulonglong2*)(hb + 2 * HH + pl * 4);
                PhD[pl] = *(const ulonglong2*)(hb + 3 * HH + pl * 4);
            }
            #pragma unroll
            for (int kc = 0; kc < 32; kc++) {
                const int bc = kc % 3;            // buffer to consume
                const int bn = (kc + 2) % 3;      // buffer to fill (free since kc-1)
                if (kc + 2 < 32) {                // issue loads BEFORE consuming
                    const int c = kc + 2;
                    Pw0[bn] = wrow0[c * GG];
                    Pw1[bn] = wrow1[c * GG];
                    Pw2[bn] = wrow2[c * GG];
                    PhA[bn] = *(const ulonglong2*)(hb + 0 * HH + c * 4);
                    PhB[bn] = *(const ulonglong2*)(hb + 1 * HH + c * 4);
                    PhC[bn] = *(const ulonglong2*)(hb + 2 * HH + c * 4);
                    PhD[bn] = *(const ulonglong2*)(hb + 3 * HH + c * 4);
                }
                fma2(a0[0], Pw0[bc].x, PhA[bc].x); fma2(a0[0], Pw0[bc].y, PhA[bc].y);
                fma2(a0[1], Pw0[bc].x, PhB[bc].x); fma2(a0[1], Pw0[bc].y, PhB[bc].y);
                fma2(a0[2], Pw0[bc].x, PhC[bc].x); fma2(a0[2], Pw0[bc].y, PhC[bc].y);
                fma2(a0[3], Pw0[bc].x, PhD[bc].x); fma2(a0[3], Pw0[bc].y, PhD[bc].y);
                fma2(a1[0], Pw1[bc].x, PhA[bc].x); fma2(a1[0], Pw1[bc].y, PhA[bc].y);
                fma2(a1[1], Pw1[bc].x, PhB[bc].x); fma2(a1[1], Pw1[bc].y, PhB[bc].y);
                fma2(a1[2], Pw1[bc].x, PhC[bc].x); fma2(a1[2], Pw1[bc].y, PhC[bc].y);
                fma2(a1[3], Pw1[bc].x, PhD[bc].x); fma2(a1[3], Pw1[bc].y, PhD[bc].y);
                fma2(a2[0], Pw2[bc].x, PhA[bc].x); fma2(a2[0], Pw2[bc].y, PhA[bc].y);
                fma2(a2[1], Pw2[bc].x, PhB[bc].x); fma2(a2[1], Pw2[bc].y, PhB[bc].y);
                fma2(a2[2], Pw2[bc].x, PhC[bc].x); fma2(a2[2], Pw2[bc].y, PhC[bc].y);
                fma2(a2[3], Pw2[bc].x, PhD[bc].x); fma2(a2[3], Pw2[bc].y, PhD[bc].y);
            }

            // ---- ih-dot: r/z from register W, n from smem W (one loop) ----
            #pragma unroll
            for (int q = 0; q < 12; q++) {
                ulonglong2 wn = winrow[q * HH];
                ulonglong2 xA = *(const ulonglong2*)(xb + 0 * DP + 4 * q);
                ulonglong2 xB = *(const ulonglong2*)(xb + 1 * DP + 4 * q);
                ulonglong2 xC = *(const ulonglong2*)(xb + 2 * DP + 4 * q);
                ulonglong2 xD = *(const ulonglong2*)(xb + 3 * DP + 4 * q);
                unsigned long long w0a = wih[0][2*q], w0b = wih[0][2*q+1];
                unsigned long long w1a = wih[1][2*q], w1b = wih[1][2*q+1];
                fma2(a0[0], w0a, xA.x); fma2(a0[0], w0b, xA.y);
                fma2(a0[1], w0a, xB.x); fma2(a0[1], w0b, xB.y);
                fma2(a0[2], w0a, xC.x); fma2(a0[2], w0b, xC.y);
                fma2(a0[3], w0a, xD.x); fma2(a0[3], w0b, xD.y);
                fma2(a1[0], w1a, xA.x); fma2(a1[0], w1b, xA.y);
                fma2(a1[1], w1a, xB.x); fma2(a1[1], w1b, xB.y);
                fma2(a1[2], w1a, xC.x); fma2(a1[2], w1b, xC.y);
                fma2(a1[3], w1a, xD.x); fma2(a1[3], w1b, xD.y);
                fma2(an[0], wn.x, xA.x); fma2(an[0], wn.y, xA.y);
                fma2(an[1], wn.x, xB.x); fma2(an[1], wn.y, xB.y);
                fma2(an[2], wn.x, xC.x); fma2(an[2], wn.y, xC.y);
                fma2(an[3], wn.x, xD.x); fma2(an[3], wn.y, xD.y);
            }

            // ---- nonlinearity + h update (MUFU) ----
            float* hn = sH + nxt * (NB * HH);
            #pragma unroll
            for (int nb = 0; nb < NB; nb++) {
                float r = fast_sig(sum2(a0[nb]));
                float z = fast_sig(sum2(a1[nb]));
                float n = fast_tanh(sum2(an[nb]) + r * sum2(a2[nb]));
                float hold = hb[nb * HH + u];
                float hv = n + z * (hold - n);
                hn[nb * HH + u] = hv;
                if (t == TT - 1)
                    out[(size_t)(b0 + nb) * HH + u] = hv;
            }
        } else {
            // ---- aux: prefetch x(t+1) ----
            if (t + 1 < TT) {
                const int a = tid - NGATE;   // 0..63
                #pragma unroll
                for (int r = 0; r < 3; r++) {
                    int idx = a + r * 64;
                    if (idx < NB * DD) {
                        int nb = idx / DD, d = idx - nb * DD;
                        sX[nxt * (NB * DP) + nb * DP + d] =
                            history[(size_t)(b0 + nb) * (TT * DD) + (t + 1) * DD + d];
                    }
                }
            }
        }

        __syncthreads();   // h(t+1) + x(t+1) visible
    }
}

extern "C" void kernel_launch(void* const* d_in, const int* in_sizes, int n_in,
                              void* d_out, int out_size) {
    const float* history = (const float*)d_in[0];
    const float* W_ih    = (const float*)d_in[1];
    const float* W_hh    = (const float*)d_in[2];
    const float* b_ih    = (const float*)d_in[3];
    const float* b_hh    = (const float*)d_in[4];
    const float* h0      = (const float*)d_in[5];
    float* out = (float*)d_out;

    cudaFuncSetAttribute(gru_v15,
                         cudaFuncAttributeMaxDynamicSharedMemorySize, SMEM_BYTES);
    gru_v15<<<NCTA, NTHR, SMEM_BYTES>>>(history, W_ih, W_hh,
                                        b_ih, b_hh, h0, out);
}